// round 15
// baseline (speedup 1.0000x reference)
#include <cuda_runtime.h>
#include <cstdint>
#include <math.h>

#define B_  8
#define T_  2048
#define C_  1024
#define H_  1024
#define SCALE_ (1.0f / 32.0f)

// GEMM tiling: CTA 128x128, 4 warps (2m x 2n), warp 64x64
#define BM 128
#define BN 128
#define BK 32
#define NTHR 128
#define A_ST_BYTES 16384
#define STAGE_BYTES 32768
#define NSTAGES 2
#define SMEM_TOTAL (STAGE_BYTES * NSTAGES)   // 65536 -> 3 CTAs/SM

#define NTK_PROD 2112u                  // qk (1088) + projV (1024) tickets
#define NTK_ALL  (NTK_PROD + 1024u)     // + pv tickets

__host__ __device__ __forceinline__ int kperm(int k) {   // pair-perm within 8
    return (k & ~7) | (((k & 3) << 1) | ((k & 7) >> 2));
}

// ---------------------------------------------------------------------------
// Scratch — operands K-pair-permuted along contraction dims.
// g_K t-rows kperm'd (S lands pre-permuted); g_VT t-cols kperm'd to match.
// ---------------------------------------------------------------------------
__device__ float g_X  [(size_t)B_ * T_ * C_];
__device__ float g_Q  [(size_t)B_ * T_ * H_];
__device__ float g_K  [(size_t)B_ * T_ * H_];
__device__ float g_VT [(size_t)B_ * H_ * T_];
__device__ float g_S  [(size_t)B_ * T_ * T_];
__device__ float g_WT [3][(size_t)H_ * C_];
__device__ float g_sum[(size_t)B_ * T_];

// Persistent-kernel scheduling state (re-zeroed by prep every call)
__device__ unsigned g_ticket;
__device__ int g_cnt_srow[B_ * 16];     // qk tiles done per (b, qb); target qb+1
__device__ int g_cnt_vt  [B_];          // projV tiles done per b; target 128

// ---------------------------------------------------------------------------
// Helpers
// ---------------------------------------------------------------------------
__device__ __forceinline__ uint32_t f2tf32(float f) {
    uint32_t r;
    asm("cvt.rna.tf32.f32 %0, %1;" : "=r"(r) : "f"(f));
    return r;
}
__device__ __forceinline__ float round_tf32(float f) {
    return __uint_as_float(f2tf32(f));
}
__device__ __forceinline__ void mma_tf32(float c[4], const uint32_t a[4],
                                         const uint32_t b[2]) {
    asm volatile(
        "mma.sync.aligned.m16n8k8.row.col.f32.tf32.tf32.f32 "
        "{%0,%1,%2,%3}, {%4,%5,%6,%7}, {%8,%9}, {%0,%1,%2,%3};"
        : "+f"(c[0]), "+f"(c[1]), "+f"(c[2]), "+f"(c[3])
        : "r"(a[0]), "r"(a[1]), "r"(a[2]), "r"(a[3]), "r"(b[0]), "r"(b[1]));
}
__device__ __forceinline__ void cp16(uint32_t d, const void* s) {
    asm volatile("cp.async.cg.shared.global [%0], [%1], 16;" :: "r"(d), "l"(s));
}
__device__ __forceinline__ void cp_commit() { asm volatile("cp.async.commit_group;"); }
__device__ __forceinline__ void cp_wait1()  { asm volatile("cp.async.wait_group 1;"); }
__device__ __forceinline__ void cp_wait0()  { asm volatile("cp.async.wait_group 0;"); }

// ---------------------------------------------------------------------------
// GEMM core (R13 structure: 2-stage cp.async, dual sync per k-tile).
// MODE 0: plain (Q/K outputs, optional t-row perm for K)
// MODE 1: qk fused softmax (exp + causal mask + row-sum atomics)
// MODE 2: pv deferred normalization
// MODE 3: V -> VT direct transposed output (t-perm, tf32-rounded)
// ---------------------------------------------------------------------------
template<int MODE>
__device__ __forceinline__ void gemm_core(const float* __restrict__ Ag, int lda,
                                          const float* __restrict__ Bg, int ldb,
                                          float* __restrict__ Cg, int ldc,
                                          int nt, float scale,
                                          const float* __restrict__ rowsum,
                                          float* __restrict__ sumatomic,
                                          int gq0, int gn0,
                                          bool round_out, bool permute_rows)
{
    extern __shared__ char dynsmem[];
    const int tid  = threadIdx.x;
    const int lane = tid & 31;
    const int wid  = tid >> 5;
    const int wm   = wid & 1;
    const int wn   = wid >> 1;
    const int g    = lane >> 2;
    const int t    = lane & 3;

    const uint32_t sb = (uint32_t)__cvta_generic_to_shared(dynsmem);
    const int r0 = tid >> 3;            // 0..15
    const int c4 = (tid & 7) << 2;      // word col 0..28

    auto issue = [&](int s, int buf) {
        const float* Abase = Ag + (size_t)s * BK;
        const float* Bbase = Bg + (size_t)s * BK;
        const uint32_t ab = sb + buf * STAGE_BYTES;
        const uint32_t bb = ab + A_ST_BYTES;
        #pragma unroll
        for (int i = 0; i < 8; i++) {
            const int r  = r0 + 16 * i;
            const int sc = c4 ^ ((r & 3) << 3);
            cp16(ab + r * 128 + sc * 4, Abase + (size_t)r * lda + c4);
            cp16(bb + r * 128 + sc * 4, Bbase + (size_t)r * ldb + c4);
        }
        cp_commit();
    };

    float acc[4][8][4];
    #pragma unroll
    for (int i = 0; i < 4; i++)
        #pragma unroll
        for (int j = 0; j < 8; j++)
            #pragma unroll
            for (int r = 0; r < 4; r++) acc[i][j][r] = 0.0f;

    issue(0, 0);
    if (nt > 1) issue(1, 1);

    const int mwb = wm * 64;
    const int nwb = wn * 64;
    const int swz = (g & 3) << 3;

    for (int s = 0; s < nt; s++) {
        if (s + 1 < nt) cp_wait1(); else cp_wait0();
        __syncthreads();   // buffer s ready

        const uint32_t* As = (const uint32_t*)(dynsmem + (s & 1) * STAGE_BYTES);
        const uint32_t* Bs = (const uint32_t*)(dynsmem + (s & 1) * STAGE_BYTES + A_ST_BYTES);

        #pragma unroll
        for (int kk8 = 0; kk8 < 4; kk8++) {
            const int cw = (kk8 * 8 + 2 * t) ^ swz;
            uint32_t ar[4][4];
            #pragma unroll
            for (int mf = 0; mf < 4; mf++) {
                const int rA = mwb + mf * 16 + g;
                uint2 v0 = *(const uint2*)&As[rA * 32 + cw];
                uint2 v1 = *(const uint2*)&As[(rA + 8) * 32 + cw];
                ar[mf][0] = v0.x; ar[mf][2] = v0.y;
                ar[mf][1] = v1.x; ar[mf][3] = v1.y;
            }
            uint32_t br[8][2];
            #pragma unroll
            for (int nf = 0; nf < 8; nf++) {
                const int rB = nwb + nf * 8 + g;
                uint2 v = *(const uint2*)&Bs[rB * 32 + cw];
                br[nf][0] = v.x; br[nf][1] = v.y;
            }
            #pragma unroll
            for (int mf = 0; mf < 4; mf++)
                #pragma unroll
                for (int nf = 0; nf < 8; nf++)
                    mma_tf32(acc[mf][nf], ar[mf], br[nf]);
        }

        __syncthreads();   // all warps done with buffer s
        if (s + 2 < nt) issue(s + 2, s & 1);
    }

    // ---- Epilogue ----
    #pragma unroll
    for (int mf = 0; mf < 4; mf++) {
        const int row = mwb + mf * 16 + g;   // low3 == g

        if (MODE == 1) {
            const int gq = gq0 + row;
            float rs0 = 0.0f, rs1 = 0.0f;
            #pragma unroll
            for (int nf = 0; nf < 8; nf++) {
                const int col = nwb + nf * 8 + 2 * t;
                const int gk0 = gn0 + nwb + nf * 8 + t;
                const int gk1 = gk0 + 4;
                float e0 = (gq     >= gk0) ? __expf(acc[mf][nf][0] * scale) : 0.0f;
                float e1 = (gq     >= gk1) ? __expf(acc[mf][nf][1] * scale) : 0.0f;
                float e2 = (gq + 8 >= gk0) ? __expf(acc[mf][nf][2] * scale) : 0.0f;
                float e3 = (gq + 8 >= gk1) ? __expf(acc[mf][nf][3] * scale) : 0.0f;
                rs0 += e0 + e1;
                rs1 += e2 + e3;
                *(float2*)&Cg[(size_t)row * ldc + col] =
                    make_float2(round_tf32(e0), round_tf32(e1));
                *(float2*)&Cg[(size_t)(row + 8) * ldc + col] =
                    make_float2(round_tf32(e2), round_tf32(e3));
            }
            rs0 += __shfl_xor_sync(0xFFFFFFFFu, rs0, 1);
            rs0 += __shfl_xor_sync(0xFFFFFFFFu, rs0, 2);
            rs1 += __shfl_xor_sync(0xFFFFFFFFu, rs1, 1);
            rs1 += __shfl_xor_sync(0xFFFFFFFFu, rs1, 2);
            if (t == 0) {
                atomicAdd(&sumatomic[row], rs0);
                atomicAdd(&sumatomic[row + 8], rs1);
            }
        } else if (MODE == 3) {
            const int tp = row - g + kperm(g);
            #pragma unroll
            for (int nf = 0; nf < 8; nf++) {
                const int col = nwb + nf * 8 + 2 * t;
                float v0 = round_tf32(acc[mf][nf][0]);
                float v1 = round_tf32(acc[mf][nf][1]);
                float v2 = round_tf32(acc[mf][nf][2]);
                float v3 = round_tf32(acc[mf][nf][3]);
                Cg[(size_t)(gn0 + col)     * ldc + tp]     = v0;
                Cg[(size_t)(gn0 + col + 1) * ldc + tp]     = v1;
                Cg[(size_t)(gn0 + col)     * ldc + tp + 8] = v2;
                Cg[(size_t)(gn0 + col + 1) * ldc + tp + 8] = v3;
            }
        } else {
            float s0 = scale, s1 = scale;
            if (MODE == 2) {
                s0 = 1.0f / rowsum[row];
                s1 = 1.0f / rowsum[row + 8];
            }
            int rw0 = row, rw1 = row + 8;
            if (MODE == 0 && permute_rows) {
                rw0 = (row - g) + kperm(g);
                rw1 = rw0 + 8;
            }
            #pragma unroll
            for (int nf = 0; nf < 8; nf++) {
                const int col = nwb + nf * 8 + 2 * t;
                float v0 = acc[mf][nf][0] * s0, v1 = acc[mf][nf][1] * s0;
                float v2 = acc[mf][nf][2] * s1, v3 = acc[mf][nf][3] * s1;
                if (round_out) {
                    v0 = round_tf32(v0); v1 = round_tf32(v1);
                    v2 = round_tf32(v2); v3 = round_tf32(v3);
                }
                *(float2*)&Cg[(size_t)rw0 * ldc + col] = make_float2(v0, v1);
                *(float2*)&Cg[(size_t)rw1 * ldc + col] = make_float2(v2, v3);
            }
        }
    }
}

// ---------------------------------------------------------------------------
// Q/K projections (z = 0,1) — unchanged standalone launch
// ---------------------------------------------------------------------------
__global__ __launch_bounds__(NTHR, 3)
void proj_qk(const float* __restrict__ W0, const float* __restrict__ W1)
{
    const int z = blockIdx.z;
    const float* WT = (z == 0) ? W0 : W1;
    float* out = (z == 0) ? g_Q : g_K;
    const size_t m0 = (size_t)blockIdx.y * BM;
    const size_t n0 = (size_t)blockIdx.x * BN;
    gemm_core<0>(g_X + m0 * C_, C_, WT + n0 * C_, C_,
                 out + m0 * H_ + n0, H_, C_ / BK, 1.0f,
                 nullptr, nullptr, 0, 0, true, z == 1);
}

// ---------------------------------------------------------------------------
// Persistent fused kernel: tickets 0..2111 = qk (1088, desc-qb) + projV (1024)
// interleaved 17:16; tickets 2112..3135 = pv (LPT desc-qb), spin-waiting on
// per-(b,qb) S-row counters and per-b VT counters.
// ---------------------------------------------------------------------------
__global__ __launch_bounds__(NTHR, 3)
void fused_attn(const float* __restrict__ W2, float* __restrict__ out)
{
    __shared__ unsigned sh_tk;

    for (;;) {
        if (threadIdx.x == 0) sh_tk = atomicAdd(&g_ticket, 1u);
        __syncthreads();                 // publish ticket; also inter-tile barrier
        const unsigned tk = sh_tk;
        __syncthreads();                 // all read before next overwrite

        if (tk >= NTK_ALL) return;

        if (tk < NTK_PROD) {
            const int group = (int)tk / 33;
            const int pos   = (int)tk % 33;

            if (pos < 17) {
                // ---- qk tile, descending qb ----
                const int i = group * 17 + pos;        // 0..1087
                const int b = i / 136;
                const int r = 135 - (i % 136);
                int qb = (int)((sqrtf(8.0f * (float)r + 1.0f) - 1.0f) * 0.5f);
                while ((qb + 1) * (qb + 2) / 2 <= r) qb++;
                while (qb * (qb + 1) / 2 > r)       qb--;
                const int kb = r - qb * (qb + 1) / 2;

                const size_t q0 = (size_t)qb * 128, n0 = (size_t)kb * 128;
                gemm_core<1>(g_Q + (size_t)b * T_ * H_ + q0 * H_, H_,
                             g_K + (size_t)b * T_ * H_ + n0 * H_, H_,
                             g_S + (size_t)b * T_ * T_ + q0 * T_ + n0, T_,
                             H_ / BK, SCALE_,
                             nullptr, g_sum + (size_t)b * T_ + q0,
                             (int)q0, (int)n0, false, false);
                // publish: S rows + g_sum contributions for (b,qb)
                __threadfence();
                __syncthreads();
                if (threadIdx.x == 0) atomicAdd(&g_cnt_srow[b * 16 + qb], 1);
            } else {
                // ---- V projection tile (writes VT directly) ----
                const int j  = group * 16 + (pos - 17);   // 0..1023
                const int nb = j & 7;
                const int mb = j >> 3;
                const size_t m0 = (size_t)mb * BM;
                const size_t n0 = (size_t)nb * BN;
                const int b  = (int)(m0 >> 11);
                const int t0 = (int)(m0 & (T_ - 1));
                gemm_core<3>(g_X + m0 * C_, C_, W2 + n0 * C_, C_,
                             g_VT + (size_t)b * H_ * T_ + t0, T_, C_ / BK, 1.0f,
                             nullptr, nullptr, 0, (int)n0, true, false);
                __threadfence();
                __syncthreads();
                if (threadIdx.x == 0) atomicAdd(&g_cnt_vt[b], 1);
            }
        } else {
            // ---- pv tile, LPT (descending qb) ----
            const int idx = (int)(tk - NTK_PROD);
            const int qb  = 15 - (idx >> 6);
            const int rem = idx & 63;
            const int b   = rem >> 3;
            const int nb  = rem & 7;

            // wait for S rows of (b,qb) [qb+1 qk tiles] and batch-b VT [128]
            if (threadIdx.x == 0) {
                while (atomicAdd(&g_cnt_srow[b * 16 + qb], 0) < qb + 1 ||
                       atomicAdd(&g_cnt_vt[b], 0) < 128)
                    __nanosleep(128);
            }
            __syncthreads();
            __threadfence();   // acquire: producer data now visible

            const size_t q0 = (size_t)qb * 128, n0 = (size_t)nb * 128;
            gemm_core<2>(g_S  + (size_t)b * T_ * T_ + q0 * T_, T_,
                         g_VT + (size_t)b * H_ * T_ + n0 * T_, T_,
                         out + (size_t)b * T_ * H_ + q0 * H_ + n0, H_,
                         (qb + 1) * 4, 1.0f,
                         g_sum + (size_t)b * T_ + q0, nullptr, 0, 0,
                         false, false);
        }
    }
}

// ---------------------------------------------------------------------------
// prep: blocks [0, 16384) convert x (tf32 + C-perm; first 64 also zero g_sum;
//       block 0 zeroes scheduler state); blocks [16384, 19456) transpose W.
// ---------------------------------------------------------------------------
__global__ __launch_bounds__(256)
void prep(const float* __restrict__ x, const float* __restrict__ Wq,
          const float* __restrict__ Wk, const float* __restrict__ Wv)
{
    __shared__ float tile[32][33];
    const int bid = blockIdx.x;

    if (bid < 16384) {
        if (bid == 0) {
            if (threadIdx.x == 0) g_ticket = 0u;
            if (threadIdx.x < B_ * 16) g_cnt_srow[threadIdx.x] = 0;
            if (threadIdx.x >= 128 && threadIdx.x < 128 + B_)
                g_cnt_vt[threadIdx.x - 128] = 0;
        }
        if (bid < (B_ * T_) / 256)
            g_sum[(size_t)bid * 256 + threadIdx.x] = 0.0f;
        const size_t i = ((size_t)bid * 256 + threadIdx.x) * 4;
        float4 v = *(const float4*)(x + i);
        const size_t base = i & ~(size_t)7;
        const int k0 = (int)(i & 7);
        g_X[base + kperm(k0 + 0)] = round_tf32(v.x);
        g_X[base + kperm(k0 + 1)] = round_tf32(v.y);
        g_X[base + kperm(k0 + 2)] = round_tf32(v.z);
        g_X[base + kperm(k0 + 3)] = round_tf32(v.w);
    } else {
        const int j = bid - 16384;             // 0..3071
        const int z = j / 1024;
        const int rest = j % 1024;
        const int bx = rest & 31;
        const int by = rest >> 5;
        const float* I = (z == 0) ? Wq : (z == 1) ? Wk : Wv;
        float* O = g_WT[z];
        const int r0 = by * 32, c0 = bx * 32;
        const int tx = threadIdx.x & 31, ty = threadIdx.x >> 5;
        #pragma unroll
        for (int i = 0; i < 32; i += 8)
            tile[ty + i][tx] = I[(size_t)(r0 + ty + i) * H_ + c0 + tx];
        __syncthreads();
        const int fp = kperm(r0 + tx);
        const int hp = (z < 2) ? kperm(ty) : ty;
        #pragma unroll
        for (int i = 0; i < 32; i += 8)
            O[(size_t)(c0 + i + hp) * C_ + fp] = round_tf32(tile[tx][ty + i]);
    }
}

// ---------------------------------------------------------------------------
// Launch
// ---------------------------------------------------------------------------
extern "C" void kernel_launch(void* const* d_in, const int* in_sizes, int n_in,
                              void* d_out, int out_size)
{
    const float* x  = (const float*)d_in[0];
    const float* Wq = (const float*)d_in[1];
    const float* Wk = (const float*)d_in[2];
    const float* Wv = (const float*)d_in[3];
    float* out = (float*)d_out;

    float* wtp;
    cudaGetSymbolAddress((void**)&wtp, g_WT);

    static int n_sm = 0;
    if (n_sm == 0) {
        cudaDeviceProp props;
        int dev;
        cudaGetDevice(&dev);
        cudaGetDeviceProperties(&props, dev);
        n_sm = props.multiProcessorCount;
    }

    cudaFuncSetAttribute(proj_qk,    cudaFuncAttributeMaxDynamicSharedMemorySize, SMEM_TOTAL);
    cudaFuncSetAttribute(fused_attn, cudaFuncAttributeMaxDynamicSharedMemorySize, SMEM_TOTAL);

    prep<<<16384 + 3072, 256>>>(x, Wq, Wk, Wv);

    dim3 gproj(H_ / BN, (B_ * T_) / BM, 2);
    proj_qk<<<gproj, NTHR, SMEM_TOTAL>>>(wtp, wtp + (size_t)H_ * C_);

    // Persistent fused qk + projV + pv (ticket-ordered, spin-synced)
    fused_attn<<<n_sm * 3, NTHR, SMEM_TOTAL>>>(wtp + 2 * (size_t)H_ * C_, out);
}

// round 16
// speedup vs baseline: 1.1075x; 1.1075x over previous
#include <cuda_runtime.h>
#include <cstdint>
#include <math.h>

#define B_  8
#define T_  2048
#define C_  1024
#define H_  1024
#define SCALE_ (1.0f / 32.0f)

// GEMM tiling: CTA 128x128, 4 warps (2m x 2n), warp 64x64
#define BM 128
#define BN 128
#define BK 32
#define NTHR 128
#define A_ST_BYTES 16384
#define STAGE_BYTES 32768
#define NSTAGES 2
#define SMEM_TOTAL (STAGE_BYTES * NSTAGES)   // 65536 -> 3 CTAs/SM

__host__ __device__ __forceinline__ int kperm(int k) {   // pair-perm within 8
    return (k & ~7) | (((k & 3) << 1) | ((k & 7) >> 2));
}

// ---------------------------------------------------------------------------
// Scratch — operands K-pair-permuted along contraction dims.
// g_K t-rows kperm'd (S lands pre-permuted); g_VT t-cols kperm'd to match.
// ---------------------------------------------------------------------------
__device__ float g_X  [(size_t)B_ * T_ * C_];
__device__ float g_Q  [(size_t)B_ * T_ * H_];
__device__ float g_K  [(size_t)B_ * T_ * H_];
__device__ float g_VT [(size_t)B_ * H_ * T_];
__device__ float g_S  [(size_t)B_ * T_ * T_];
__device__ float g_WT [3][(size_t)H_ * C_];
__device__ float g_sum[(size_t)B_ * T_];

// ---------------------------------------------------------------------------
// Helpers
// ---------------------------------------------------------------------------
__device__ __forceinline__ uint32_t f2tf32(float f) {
    uint32_t r;
    asm("cvt.rna.tf32.f32 %0, %1;" : "=r"(r) : "f"(f));
    return r;
}
__device__ __forceinline__ float round_tf32(float f) {
    return __uint_as_float(f2tf32(f));
}
__device__ __forceinline__ float ex2_approx(float f) {
    float r;
    asm("ex2.approx.f32 %0, %1;" : "=f"(r) : "f"(f));
    return r;
}
__device__ __forceinline__ void mma_tf32(float c[4], const uint32_t a[4],
                                         const uint32_t b[2]) {
    asm volatile(
        "mma.sync.aligned.m16n8k8.row.col.f32.tf32.tf32.f32 "
        "{%0,%1,%2,%3}, {%4,%5,%6,%7}, {%8,%9}, {%0,%1,%2,%3};"
        : "+f"(c[0]), "+f"(c[1]), "+f"(c[2]), "+f"(c[3])
        : "r"(a[0]), "r"(a[1]), "r"(a[2]), "r"(a[3]), "r"(b[0]), "r"(b[1]));
}
__device__ __forceinline__ void cp16(uint32_t d, const void* s) {
    asm volatile("cp.async.cg.shared.global [%0], [%1], 16;" :: "r"(d), "l"(s));
}
__device__ __forceinline__ void cp_commit() { asm volatile("cp.async.commit_group;"); }
__device__ __forceinline__ void cp_wait1()  { asm volatile("cp.async.wait_group 1;"); }
__device__ __forceinline__ void cp_wait0()  { asm volatile("cp.async.wait_group 0;"); }

// ---------------------------------------------------------------------------
// GEMM core (R13 structure: 2-stage cp.async, dual sync per k-tile).
// MODE 0: plain (Q/K outputs, optional t-row perm for K)
// MODE 1: qk fused softmax (ex2 + causal mask + row-sum atomics)
// MODE 2: pv deferred normalization
// MODE 3: V -> VT direct transposed output (t-perm, tf32-rounded)
// ---------------------------------------------------------------------------
template<int MODE>
__device__ __forceinline__ void gemm_core(const float* __restrict__ Ag, int lda,
                                          const float* __restrict__ Bg, int ldb,
                                          float* __restrict__ Cg, int ldc,
                                          int nt, float scale,
                                          const float* __restrict__ rowsum,
                                          float* __restrict__ sumatomic,
                                          int gq0, int gn0,
                                          bool round_out, bool permute_rows)
{
    extern __shared__ char dynsmem[];
    const int tid  = threadIdx.x;
    const int lane = tid & 31;
    const int wid  = tid >> 5;
    const int wm   = wid & 1;
    const int wn   = wid >> 1;
    const int g    = lane >> 2;
    const int t    = lane & 3;

    const uint32_t sb = (uint32_t)__cvta_generic_to_shared(dynsmem);
    const int r0 = tid >> 3;            // 0..15
    const int c4 = (tid & 7) << 2;      // word col 0..28

    auto issue = [&](int s, int buf) {
        const float* Abase = Ag + (size_t)s * BK;
        const float* Bbase = Bg + (size_t)s * BK;
        const uint32_t ab = sb + buf * STAGE_BYTES;
        const uint32_t bb = ab + A_ST_BYTES;
        #pragma unroll
        for (int i = 0; i < 8; i++) {
            const int r  = r0 + 16 * i;
            const int sc = c4 ^ ((r & 3) << 3);
            cp16(ab + r * 128 + sc * 4, Abase + (size_t)r * lda + c4);
            cp16(bb + r * 128 + sc * 4, Bbase + (size_t)r * ldb + c4);
        }
        cp_commit();
    };

    float acc[4][8][4];
    #pragma unroll
    for (int i = 0; i < 4; i++)
        #pragma unroll
        for (int j = 0; j < 8; j++)
            #pragma unroll
            for (int r = 0; r < 4; r++) acc[i][j][r] = 0.0f;

    issue(0, 0);
    if (nt > 1) issue(1, 1);

    const int mwb = wm * 64;
    const int nwb = wn * 64;
    const int swz = (g & 3) << 3;

    for (int s = 0; s < nt; s++) {
        if (s + 1 < nt) cp_wait1(); else cp_wait0();
        __syncthreads();   // buffer s ready

        const uint32_t* As = (const uint32_t*)(dynsmem + (s & 1) * STAGE_BYTES);
        const uint32_t* Bs = (const uint32_t*)(dynsmem + (s & 1) * STAGE_BYTES + A_ST_BYTES);

        #pragma unroll
        for (int kk8 = 0; kk8 < 4; kk8++) {
            const int cw = (kk8 * 8 + 2 * t) ^ swz;
            uint32_t ar[4][4];
            #pragma unroll
            for (int mf = 0; mf < 4; mf++) {
                const int rA = mwb + mf * 16 + g;
                uint2 v0 = *(const uint2*)&As[rA * 32 + cw];
                uint2 v1 = *(const uint2*)&As[(rA + 8) * 32 + cw];
                ar[mf][0] = v0.x; ar[mf][2] = v0.y;
                ar[mf][1] = v1.x; ar[mf][3] = v1.y;
            }
            uint32_t br[8][2];
            #pragma unroll
            for (int nf = 0; nf < 8; nf++) {
                const int rB = nwb + nf * 8 + g;
                uint2 v = *(const uint2*)&Bs[rB * 32 + cw];
                br[nf][0] = v.x; br[nf][1] = v.y;
            }
            #pragma unroll
            for (int mf = 0; mf < 4; mf++)
                #pragma unroll
                for (int nf = 0; nf < 8; nf++)
                    mma_tf32(acc[mf][nf], ar[mf], br[nf]);
        }

        __syncthreads();   // all warps done with buffer s
        if (s + 2 < nt) issue(s + 2, s & 1);
    }

    // ---- Epilogue ----
    #pragma unroll
    for (int mf = 0; mf < 4; mf++) {
        const int row = mwb + mf * 16 + g;   // low3 == g

        if (MODE == 1) {
            // exp folded: exp(acc*SCALE) = ex2(acc * SCALE*log2e)
            const float SC2 = scale * 1.4426950408889634f;
            const int gq = gq0 + row;
            float rs0 = 0.0f, rs1 = 0.0f;
            #pragma unroll
            for (int nf = 0; nf < 8; nf++) {
                const int col = nwb + nf * 8 + 2 * t;
                const int gk0 = gn0 + nwb + nf * 8 + t;
                const int gk1 = gk0 + 4;
                float e0 = (gq     >= gk0) ? ex2_approx(acc[mf][nf][0] * SC2) : 0.0f;
                float e1 = (gq     >= gk1) ? ex2_approx(acc[mf][nf][1] * SC2) : 0.0f;
                float e2 = (gq + 8 >= gk0) ? ex2_approx(acc[mf][nf][2] * SC2) : 0.0f;
                float e3 = (gq + 8 >= gk1) ? ex2_approx(acc[mf][nf][3] * SC2) : 0.0f;
                rs0 += e0 + e1;
                rs1 += e2 + e3;
                *(float2*)&Cg[(size_t)row * ldc + col] =
                    make_float2(round_tf32(e0), round_tf32(e1));
                *(float2*)&Cg[(size_t)(row + 8) * ldc + col] =
                    make_float2(round_tf32(e2), round_tf32(e3));
            }
            rs0 += __shfl_xor_sync(0xFFFFFFFFu, rs0, 1);
            rs0 += __shfl_xor_sync(0xFFFFFFFFu, rs0, 2);
            rs1 += __shfl_xor_sync(0xFFFFFFFFu, rs1, 1);
            rs1 += __shfl_xor_sync(0xFFFFFFFFu, rs1, 2);
            if (t == 0) {
                atomicAdd(&sumatomic[row], rs0);
                atomicAdd(&sumatomic[row + 8], rs1);
            }
        } else if (MODE == 3) {
            const int tp = row - g + kperm(g);
            #pragma unroll
            for (int nf = 0; nf < 8; nf++) {
                const int col = nwb + nf * 8 + 2 * t;
                float v0 = round_tf32(acc[mf][nf][0]);
                float v1 = round_tf32(acc[mf][nf][1]);
                float v2 = round_tf32(acc[mf][nf][2]);
                float v3 = round_tf32(acc[mf][nf][3]);
                Cg[(size_t)(gn0 + col)     * ldc + tp]     = v0;
                Cg[(size_t)(gn0 + col + 1) * ldc + tp]     = v1;
                Cg[(size_t)(gn0 + col)     * ldc + tp + 8] = v2;
                Cg[(size_t)(gn0 + col + 1) * ldc + tp + 8] = v3;
            }
        } else {
            float s0 = scale, s1 = scale;
            if (MODE == 2) {
                s0 = __fdividef(1.0f, rowsum[row]);
                s1 = __fdividef(1.0f, rowsum[row + 8]);
            }
            int rw0 = row, rw1 = row + 8;
            if (MODE == 0 && permute_rows) {
                rw0 = (row - g) + kperm(g);
                rw1 = rw0 + 8;
            }
            #pragma unroll
            for (int nf = 0; nf < 8; nf++) {
                const int col = nwb + nf * 8 + 2 * t;
                float v0 = acc[mf][nf][0] * s0, v1 = acc[mf][nf][1] * s0;
                float v2 = acc[mf][nf][2] * s1, v3 = acc[mf][nf][3] * s1;
                if (round_out) {
                    v0 = round_tf32(v0); v1 = round_tf32(v1);
                    v2 = round_tf32(v2); v3 = round_tf32(v3);
                }
                *(float2*)&Cg[(size_t)rw0 * ldc + col] = make_float2(v0, v1);
                *(float2*)&Cg[(size_t)rw1 * ldc + col] = make_float2(v2, v3);
            }
        }
    }
}

// ---------------------------------------------------------------------------
// Q/K projections only (z = 0,1)
// ---------------------------------------------------------------------------
__global__ __launch_bounds__(NTHR, 3)
void proj_qk(const float* __restrict__ W0, const float* __restrict__ W1)
{
    const int z = blockIdx.z;
    const float* WT = (z == 0) ? W0 : W1;
    float* out = (z == 0) ? g_Q : g_K;
    const size_t m0 = (size_t)blockIdx.y * BM;
    const size_t n0 = (size_t)blockIdx.x * BN;
    gemm_core<0>(g_X + m0 * C_, C_, WT + n0 * C_, C_,
                 out + m0 * H_ + n0, H_, C_ / BK, 1.0f,
                 nullptr, nullptr, 0, 0, true, z == 1);
}

// ---------------------------------------------------------------------------
// Merged launch: 1088 triangular qk tiles (big-qb first) + 1024 V-projection
// tiles, interleaved in 33-block groups (17 qk + 16 projV). Grid.x = 2112.
// ---------------------------------------------------------------------------
__global__ __launch_bounds__(NTHR, 3)
void qk_projv(const float* __restrict__ W2)
{
    const int idx   = blockIdx.x;
    const int group = idx / 33;
    const int pos   = idx % 33;

    if (pos < 17) {
        const int i = group * 17 + pos;        // 0..1087
        const int b = i / 136;
        const int r = 135 - (i % 136);         // reverse -> qb descends
        int qb = (int)((sqrtf(8.0f * (float)r + 1.0f) - 1.0f) * 0.5f);
        while ((qb + 1) * (qb + 2) / 2 <= r) qb++;
        while (qb * (qb + 1) / 2 > r)       qb--;
        const int kb = r - qb * (qb + 1) / 2;

        const size_t q0 = (size_t)qb * 128, n0 = (size_t)kb * 128;
        gemm_core<1>(g_Q + (size_t)b * T_ * H_ + q0 * H_, H_,
                     g_K + (size_t)b * T_ * H_ + n0 * H_, H_,
                     g_S + (size_t)b * T_ * T_ + q0 * T_ + n0, T_,
                     H_ / BK, SCALE_,
                     nullptr, g_sum + (size_t)b * T_ + q0, (int)q0, (int)n0,
                     false, false);
    } else {
        const int j  = group * 16 + (pos - 17);   // 0..1023
        const int nb = j & 7;
        const int mb = j >> 3;
        const size_t m0 = (size_t)mb * BM;
        const size_t n0 = (size_t)nb * BN;
        const int b  = (int)(m0 >> 11);
        const int t0 = (int)(m0 & (T_ - 1));
        gemm_core<3>(g_X + m0 * C_, C_, W2 + n0 * C_, C_,
                     g_VT + (size_t)b * H_ * T_ + t0, T_, C_ / BK, 1.0f,
                     nullptr, nullptr, 0, (int)n0, true, false);
    }
}

// ---------------------------------------------------------------------------
// pv: 1D grid 1024, qb DESCENDING (longest-processing-time-first)
// ---------------------------------------------------------------------------
__global__ __launch_bounds__(NTHR, 3)
void pv_mma(float* __restrict__ out)
{
    const int idx = blockIdx.x;
    const int qb  = 15 - (idx >> 6);
    const int rem = idx & 63;
    const int b   = rem >> 3;
    const int nb  = rem & 7;
    const size_t q0 = (size_t)qb * 128, n0 = (size_t)nb * 128;
    gemm_core<2>(g_S  + (size_t)b * T_ * T_ + q0 * T_, T_,
                 g_VT + (size_t)b * H_ * T_ + n0 * T_, T_,
                 out + (size_t)b * T_ * H_ + q0 * H_ + n0, H_,
                 (qb + 1) * 4, 1.0f,
                 g_sum + (size_t)b * T_ + q0, nullptr, 0, 0,
                 false, false);
}

// ---------------------------------------------------------------------------
// prep: blocks [0, 16384) convert x (tf32 + C-perm via lane-pair exchange ->
//       full float4 stores; first 64 blocks also zero g_sum);
//       blocks [16384, 19456) transpose W (C cols perm; Wq/Wk h rows perm)
// ---------------------------------------------------------------------------
__global__ __launch_bounds__(256)
void prep(const float* __restrict__ x, const float* __restrict__ Wq,
          const float* __restrict__ Wk, const float* __restrict__ Wv)
{
    __shared__ float tile[32][33];
    const int bid = blockIdx.x;

    if (bid < 16384) {
        if (bid < (B_ * T_) / 256)
            g_sum[(size_t)bid * 256 + threadIdx.x] = 0.0f;
        const size_t i = ((size_t)bid * 256 + threadIdx.x) * 4;
        float4 v = *(const float4*)(x + i);
        v.x = round_tf32(v.x); v.y = round_tf32(v.y);
        v.z = round_tf32(v.z); v.w = round_tf32(v.w);
        // lane-pair exchange: even lane holds x0..x3 of an 8-group, odd holds
        // x4..x7. stored[] = {x0,x4,x1,x5, x2,x6,x3,x7}.
        const float ox = __shfl_xor_sync(0xFFFFFFFFu, v.x, 1);
        const float oy = __shfl_xor_sync(0xFFFFFFFFu, v.y, 1);
        const float oz = __shfl_xor_sync(0xFFFFFFFFu, v.z, 1);
        const float ow = __shfl_xor_sync(0xFFFFFFFFu, v.w, 1);
        float4 outv;
        if ((threadIdx.x & 1) == 0)
            outv = make_float4(v.x, ox, v.y, oy);   // stored[0..3]
        else
            outv = make_float4(oz, v.z, ow, v.w);   // stored[4..7]
        *(float4*)&g_X[i] = outv;                   // i is 16B-aligned
    } else {
        const int j = bid - 16384;             // 0..3071
        const int z = j / 1024;
        const int rest = j % 1024;
        const int bx = rest & 31;
        const int by = rest >> 5;
        const float* I = (z == 0) ? Wq : (z == 1) ? Wk : Wv;
        float* O = g_WT[z];
        const int r0 = by * 32, c0 = bx * 32;
        const int tx = threadIdx.x & 31, ty = threadIdx.x >> 5;
        #pragma unroll
        for (int i = 0; i < 32; i += 8)
            tile[ty + i][tx] = I[(size_t)(r0 + ty + i) * H_ + c0 + tx];
        __syncthreads();
        const int fp = kperm(r0 + tx);
        const int hp = (z < 2) ? kperm(ty) : ty;
        #pragma unroll
        for (int i = 0; i < 32; i += 8)
            O[(size_t)(c0 + i + hp) * C_ + fp] = round_tf32(tile[tx][ty + i]);
    }
}

// ---------------------------------------------------------------------------
// Launch
// ---------------------------------------------------------------------------
extern "C" void kernel_launch(void* const* d_in, const int* in_sizes, int n_in,
                              void* d_out, int out_size)
{
    const float* x  = (const float*)d_in[0];
    const float* Wq = (const float*)d_in[1];
    const float* Wk = (const float*)d_in[2];
    const float* Wv = (const float*)d_in[3];
    float* out = (float*)d_out;

    float* wtp;
    cudaGetSymbolAddress((void**)&wtp, g_WT);

    cudaFuncSetAttribute(proj_qk,  cudaFuncAttributeMaxDynamicSharedMemorySize, SMEM_TOTAL);
    cudaFuncSetAttribute(qk_projv, cudaFuncAttributeMaxDynamicSharedMemorySize, SMEM_TOTAL);
    cudaFuncSetAttribute(pv_mma,   cudaFuncAttributeMaxDynamicSharedMemorySize, SMEM_TOTAL);

    prep<<<16384 + 3072, 256>>>(x, Wq, Wk, Wv);

    dim3 gproj(H_ / BN, (B_ * T_) / BM, 2);
    proj_qk<<<gproj, NTHR, SMEM_TOTAL>>>(wtp, wtp + (size_t)H_ * C_);

    qk_projv<<<2112, NTHR, SMEM_TOTAL>>>(wtp + 2 * (size_t)H_ * C_);

    pv_mma<<<1024, NTHR, SMEM_TOTAL>>>(out);
}

// round 17
// speedup vs baseline: 1.1129x; 1.0048x over previous
#include <cuda_runtime.h>
#include <cstdint>
#include <math.h>

#define B_  8
#define T_  2048
#define C_  1024
#define H_  1024
#define SCALE_ (1.0f / 32.0f)

// GEMM tiling: CTA 128x128, 4 warps (2m x 2n), warp 64x64
#define BM 128
#define BN 128
#define BK 32
#define NTHR 128
#define A_ST_BYTES 16384
#define STAGE_BYTES 32768
#define NSTAGES 2
#define SMEM_TOTAL (STAGE_BYTES * NSTAGES)   // 65536 -> 3 CTAs/SM

__host__ __device__ __forceinline__ int kperm(int k) {   // pair-perm within 8
    return (k & ~7) | (((k & 3) << 1) | ((k & 7) >> 2));
}

// ---------------------------------------------------------------------------
// Scratch — operands K-pair-permuted along contraction dims.
// g_K t-rows kperm'd (S lands pre-permuted); g_VT t-cols kperm'd to match.
// ---------------------------------------------------------------------------
__device__ float g_X  [(size_t)B_ * T_ * C_];
__device__ float g_Q  [(size_t)B_ * T_ * H_];
__device__ float g_K  [(size_t)B_ * T_ * H_];
__device__ float g_VT [(size_t)B_ * H_ * T_];
__device__ float g_S  [(size_t)B_ * T_ * T_];
__device__ float g_WT [3][(size_t)H_ * C_];
__device__ float g_sum[(size_t)B_ * T_];

// ---------------------------------------------------------------------------
// Helpers
// ---------------------------------------------------------------------------
__device__ __forceinline__ uint32_t f2tf32(float f) {
    uint32_t r;
    asm("cvt.rna.tf32.f32 %0, %1;" : "=r"(r) : "f"(f));
    return r;
}
__device__ __forceinline__ float round_tf32(float f) {
    return __uint_as_float(f2tf32(f));
}
__device__ __forceinline__ float ex2_approx(float f) {
    float r;
    asm("ex2.approx.f32 %0, %1;" : "=f"(r) : "f"(f));
    return r;
}
__device__ __forceinline__ void mma_tf32(float c[4], const uint32_t a[4],
                                         const uint32_t b[2]) {
    asm volatile(
        "mma.sync.aligned.m16n8k8.row.col.f32.tf32.tf32.f32 "
        "{%0,%1,%2,%3}, {%4,%5,%6,%7}, {%8,%9}, {%0,%1,%2,%3};"
        : "+f"(c[0]), "+f"(c[1]), "+f"(c[2]), "+f"(c[3])
        : "r"(a[0]), "r"(a[1]), "r"(a[2]), "r"(a[3]), "r"(b[0]), "r"(b[1]));
}
__device__ __forceinline__ void cp16(uint32_t d, const void* s) {
    asm volatile("cp.async.cg.shared.global [%0], [%1], 16;" :: "r"(d), "l"(s));
}
__device__ __forceinline__ void cp_commit() { asm volatile("cp.async.commit_group;"); }
__device__ __forceinline__ void cp_wait1()  { asm volatile("cp.async.wait_group 1;"); }
__device__ __forceinline__ void cp_wait0()  { asm volatile("cp.async.wait_group 0;"); }

// Paired-lane float4 store: lanes t and t^1 (same g) exchange their rounded
// column pairs; even t stores the row-float4, odd t stores the (row+8)-float4.
// col4 = nf-base + ((t&2)<<1) covers 4 consecutive columns.
__device__ __forceinline__ void paired_store(float* __restrict__ Cg, int ldc,
                                             int rowA, int rowB, int col4,
                                             int t, float v0, float v1,
                                             float v2, float v3)
{
    const float p0 = __shfl_xor_sync(0xFFFFFFFFu, v0, 1);
    const float p1 = __shfl_xor_sync(0xFFFFFFFFu, v1, 1);
    const float p2 = __shfl_xor_sync(0xFFFFFFFFu, v2, 1);
    const float p3 = __shfl_xor_sync(0xFFFFFFFFu, v3, 1);
    if ((t & 1) == 0)
        *(float4*)&Cg[(size_t)rowA * ldc + col4] = make_float4(v0, v1, p0, p1);
    else
        *(float4*)&Cg[(size_t)rowB * ldc + col4] = make_float4(p2, p3, v2, v3);
}

// ---------------------------------------------------------------------------
// GEMM core (R13 structure: 2-stage cp.async, dual sync per k-tile).
// MODE 0: plain (Q/K outputs, optional t-row perm for K)
// MODE 1: qk fused softmax (ex2 + causal mask + row-sum atomics)
// MODE 2: pv deferred normalization
// MODE 3: V -> VT direct transposed output (t-perm, tf32-rounded)
// ---------------------------------------------------------------------------
template<int MODE>
__device__ __forceinline__ void gemm_core(const float* __restrict__ Ag, int lda,
                                          const float* __restrict__ Bg, int ldb,
                                          float* __restrict__ Cg, int ldc,
                                          int nt, float scale,
                                          const float* __restrict__ rowsum,
                                          float* __restrict__ sumatomic,
                                          int gq0, int gn0,
                                          bool round_out, bool permute_rows)
{
    extern __shared__ char dynsmem[];
    const int tid  = threadIdx.x;
    const int lane = tid & 31;
    const int wid  = tid >> 5;
    const int wm   = wid & 1;
    const int wn   = wid >> 1;
    const int g    = lane >> 2;
    const int t    = lane & 3;

    const uint32_t sb = (uint32_t)__cvta_generic_to_shared(dynsmem);
    const int r0 = tid >> 3;            // 0..15
    const int c4 = (tid & 7) << 2;      // word col 0..28

    auto issue = [&](int s, int buf) {
        const float* Abase = Ag + (size_t)s * BK;
        const float* Bbase = Bg + (size_t)s * BK;
        const uint32_t ab = sb + buf * STAGE_BYTES;
        const uint32_t bb = ab + A_ST_BYTES;
        #pragma unroll
        for (int i = 0; i < 8; i++) {
            const int r  = r0 + 16 * i;
            const int sc = c4 ^ ((r & 3) << 3);
            cp16(ab + r * 128 + sc * 4, Abase + (size_t)r * lda + c4);
            cp16(bb + r * 128 + sc * 4, Bbase + (size_t)r * ldb + c4);
        }
        cp_commit();
    };

    float acc[4][8][4];
    #pragma unroll
    for (int i = 0; i < 4; i++)
        #pragma unroll
        for (int j = 0; j < 8; j++)
            #pragma unroll
            for (int r = 0; r < 4; r++) acc[i][j][r] = 0.0f;

    issue(0, 0);
    if (nt > 1) issue(1, 1);

    const int mwb = wm * 64;
    const int nwb = wn * 64;
    const int swz = (g & 3) << 3;

    for (int s = 0; s < nt; s++) {
        if (s + 1 < nt) cp_wait1(); else cp_wait0();
        __syncthreads();   // buffer s ready

        const uint32_t* As = (const uint32_t*)(dynsmem + (s & 1) * STAGE_BYTES);
        const uint32_t* Bs = (const uint32_t*)(dynsmem + (s & 1) * STAGE_BYTES + A_ST_BYTES);

        #pragma unroll
        for (int kk8 = 0; kk8 < 4; kk8++) {
            const int cw = (kk8 * 8 + 2 * t) ^ swz;
            uint32_t ar[4][4];
            #pragma unroll
            for (int mf = 0; mf < 4; mf++) {
                const int rA = mwb + mf * 16 + g;
                uint2 v0 = *(const uint2*)&As[rA * 32 + cw];
                uint2 v1 = *(const uint2*)&As[(rA + 8) * 32 + cw];
                ar[mf][0] = v0.x; ar[mf][2] = v0.y;
                ar[mf][1] = v1.x; ar[mf][3] = v1.y;
            }
            uint32_t br[8][2];
            #pragma unroll
            for (int nf = 0; nf < 8; nf++) {
                const int rB = nwb + nf * 8 + g;
                uint2 v = *(const uint2*)&Bs[rB * 32 + cw];
                br[nf][0] = v.x; br[nf][1] = v.y;
            }
            #pragma unroll
            for (int mf = 0; mf < 4; mf++)
                #pragma unroll
                for (int nf = 0; nf < 8; nf++)
                    mma_tf32(acc[mf][nf], ar[mf], br[nf]);
        }

        __syncthreads();   // all warps done with buffer s
        if (s + 2 < nt) issue(s + 2, s & 1);
    }

    // ---- Epilogue (paired-lane float4 stores) ----
    #pragma unroll
    for (int mf = 0; mf < 4; mf++) {
        const int row = mwb + mf * 16 + g;   // low3 == g

        if (MODE == 1) {
            // exp folded: exp(acc*SCALE) = ex2(acc * SCALE*log2e)
            const float SC2 = scale * 1.4426950408889634f;
            const int gq = gq0 + row;
            float rs0 = 0.0f, rs1 = 0.0f;
            #pragma unroll
            for (int nf = 0; nf < 8; nf++) {
                const int col4 = nwb + nf * 8 + ((t & 2) << 1);
                const int gk0 = gn0 + nwb + nf * 8 + t;
                const int gk1 = gk0 + 4;
                float e0 = (gq     >= gk0) ? ex2_approx(acc[mf][nf][0] * SC2) : 0.0f;
                float e1 = (gq     >= gk1) ? ex2_approx(acc[mf][nf][1] * SC2) : 0.0f;
                float e2 = (gq + 8 >= gk0) ? ex2_approx(acc[mf][nf][2] * SC2) : 0.0f;
                float e3 = (gq + 8 >= gk1) ? ex2_approx(acc[mf][nf][3] * SC2) : 0.0f;
                rs0 += e0 + e1;
                rs1 += e2 + e3;
                paired_store(Cg, ldc, row, row + 8, col4, t,
                             round_tf32(e0), round_tf32(e1),
                             round_tf32(e2), round_tf32(e3));
            }
            rs0 += __shfl_xor_sync(0xFFFFFFFFu, rs0, 1);
            rs0 += __shfl_xor_sync(0xFFFFFFFFu, rs0, 2);
            rs1 += __shfl_xor_sync(0xFFFFFFFFu, rs1, 1);
            rs1 += __shfl_xor_sync(0xFFFFFFFFu, rs1, 2);
            if (t == 0) {
                atomicAdd(&sumatomic[row], rs0);
                atomicAdd(&sumatomic[row + 8], rs1);
            }
        } else if (MODE == 3) {
            const int tp = row - g + kperm(g);
            #pragma unroll
            for (int nf = 0; nf < 8; nf++) {
                const int col = nwb + nf * 8 + 2 * t;
                float v0 = round_tf32(acc[mf][nf][0]);
                float v1 = round_tf32(acc[mf][nf][1]);
                float v2 = round_tf32(acc[mf][nf][2]);
                float v3 = round_tf32(acc[mf][nf][3]);
                Cg[(size_t)(gn0 + col)     * ldc + tp]     = v0;
                Cg[(size_t)(gn0 + col + 1) * ldc + tp]     = v1;
                Cg[(size_t)(gn0 + col)     * ldc + tp + 8] = v2;
                Cg[(size_t)(gn0 + col + 1) * ldc + tp + 8] = v3;
            }
        } else {
            float s0 = scale, s1 = scale;
            if (MODE == 2) {
                s0 = __fdividef(1.0f, rowsum[row]);
                s1 = __fdividef(1.0f, rowsum[row + 8]);
            }
            int rw0 = row, rw1 = row + 8;
            if (MODE == 0 && permute_rows) {
                rw0 = (row - g) + kperm(g);
                rw1 = rw0 + 8;
            }
            #pragma unroll
            for (int nf = 0; nf < 8; nf++) {
                const int col4 = nwb + nf * 8 + ((t & 2) << 1);
                float v0 = acc[mf][nf][0] * s0, v1 = acc[mf][nf][1] * s0;
                float v2 = acc[mf][nf][2] * s1, v3 = acc[mf][nf][3] * s1;
                if (round_out) {
                    v0 = round_tf32(v0); v1 = round_tf32(v1);
                    v2 = round_tf32(v2); v3 = round_tf32(v3);
                }
                paired_store(Cg, ldc, rw0, rw1, col4, t, v0, v1, v2, v3);
            }
        }
    }
}

// ---------------------------------------------------------------------------
// Q/K projections only (z = 0,1)
// ---------------------------------------------------------------------------
__global__ __launch_bounds__(NTHR, 3)
void proj_qk(const float* __restrict__ W0, const float* __restrict__ W1)
{
    const int z = blockIdx.z;
    const float* WT = (z == 0) ? W0 : W1;
    float* out = (z == 0) ? g_Q : g_K;
    const size_t m0 = (size_t)blockIdx.y * BM;
    const size_t n0 = (size_t)blockIdx.x * BN;
    gemm_core<0>(g_X + m0 * C_, C_, WT + n0 * C_, C_,
                 out + m0 * H_ + n0, H_, C_ / BK, 1.0f,
                 nullptr, nullptr, 0, 0, true, z == 1);
}

// ---------------------------------------------------------------------------
// Merged launch: 1088 triangular qk tiles (big-qb first) + 1024 V-projection
// tiles, interleaved in 33-block groups (17 qk + 16 projV). Grid.x = 2112.
// ---------------------------------------------------------------------------
__global__ __launch_bounds__(NTHR, 3)
void qk_projv(const float* __restrict__ W2)
{
    const int idx   = blockIdx.x;
    const int group = idx / 33;
    const int pos   = idx % 33;

    if (pos < 17) {
        const int i = group * 17 + pos;        // 0..1087
        const int b = i / 136;
        const int r = 135 - (i % 136);         // reverse -> qb descends
        int qb = (int)((sqrtf(8.0f * (float)r + 1.0f) - 1.0f) * 0.5f);
        while ((qb + 1) * (qb + 2) / 2 <= r) qb++;
        while (qb * (qb + 1) / 2 > r)       qb--;
        const int kb = r - qb * (qb + 1) / 2;

        const size_t q0 = (size_t)qb * 128, n0 = (size_t)kb * 128;
        gemm_core<1>(g_Q + (size_t)b * T_ * H_ + q0 * H_, H_,
                     g_K + (size_t)b * T_ * H_ + n0 * H_, H_,
                     g_S + (size_t)b * T_ * T_ + q0 * T_ + n0, T_,
                     H_ / BK, SCALE_,
                     nullptr, g_sum + (size_t)b * T_ + q0, (int)q0, (int)n0,
                     false, false);
    } else {
        const int j  = group * 16 + (pos - 17);   // 0..1023
        const int nb = j & 7;
        const int mb = j >> 3;
        const size_t m0 = (size_t)mb * BM;
        const size_t n0 = (size_t)nb * BN;
        const int b  = (int)(m0 >> 11);
        const int t0 = (int)(m0 & (T_ - 1));
        gemm_core<3>(g_X + m0 * C_, C_, W2 + n0 * C_, C_,
                     g_VT + (size_t)b * H_ * T_ + t0, T_, C_ / BK, 1.0f,
                     nullptr, nullptr, 0, (int)n0, true, false);
    }
}

// ---------------------------------------------------------------------------
// pv: 1D grid 1024, qb DESCENDING (longest-processing-time-first)
// ---------------------------------------------------------------------------
__global__ __launch_bounds__(NTHR, 3)
void pv_mma(float* __restrict__ out)
{
    const int idx = blockIdx.x;
    const int qb  = 15 - (idx >> 6);
    const int rem = idx & 63;
    const int b   = rem >> 3;
    const int nb  = rem & 7;
    const size_t q0 = (size_t)qb * 128, n0 = (size_t)nb * 128;
    gemm_core<2>(g_S  + (size_t)b * T_ * T_ + q0 * T_, T_,
                 g_VT + (size_t)b * H_ * T_ + n0 * T_, T_,
                 out + (size_t)b * T_ * H_ + q0 * H_ + n0, H_,
                 (qb + 1) * 4, 1.0f,
                 g_sum + (size_t)b * T_ + q0, nullptr, 0, 0,
                 false, false);
}

// ---------------------------------------------------------------------------
// prep: blocks [0, 16384) convert x (tf32 + C-perm via lane-pair exchange ->
//       full float4 stores; first 64 blocks also zero g_sum);
//       blocks [16384, 19456) transpose W (C cols perm; Wq/Wk h rows perm)
// ---------------------------------------------------------------------------
__global__ __launch_bounds__(256)
void prep(const float* __restrict__ x, const float* __restrict__ Wq,
          const float* __restrict__ Wk, const float* __restrict__ Wv)
{
    __shared__ float tile[32][33];
    const int bid = blockIdx.x;

    if (bid < 16384) {
        if (bid < (B_ * T_) / 256)
            g_sum[(size_t)bid * 256 + threadIdx.x] = 0.0f;
        const size_t i = ((size_t)bid * 256 + threadIdx.x) * 4;
        float4 v = *(const float4*)(x + i);
        v.x = round_tf32(v.x); v.y = round_tf32(v.y);
        v.z = round_tf32(v.z); v.w = round_tf32(v.w);
        const float ox = __shfl_xor_sync(0xFFFFFFFFu, v.x, 1);
        const float oy = __shfl_xor_sync(0xFFFFFFFFu, v.y, 1);
        const float oz = __shfl_xor_sync(0xFFFFFFFFu, v.z, 1);
        const float ow = __shfl_xor_sync(0xFFFFFFFFu, v.w, 1);
        float4 outv;
        if ((threadIdx.x & 1) == 0)
            outv = make_float4(v.x, ox, v.y, oy);   // stored[0..3]
        else
            outv = make_float4(oz, v.z, ow, v.w);   // stored[4..7]
        *(float4*)&g_X[i] = outv;
    } else {
        const int j = bid - 16384;             // 0..3071
        const int z = j / 1024;
        const int rest = j % 1024;
        const int bx = rest & 31;
        const int by = rest >> 5;
        const float* I = (z == 0) ? Wq : (z == 1) ? Wk : Wv;
        float* O = g_WT[z];
        const int r0 = by * 32, c0 = bx * 32;
        const int tx = threadIdx.x & 31, ty = threadIdx.x >> 5;
        #pragma unroll
        for (int i = 0; i < 32; i += 8)
            tile[ty + i][tx] = I[(size_t)(r0 + ty + i) * H_ + c0 + tx];
        __syncthreads();
        const int fp = kperm(r0 + tx);
        const int hp = (z < 2) ? kperm(ty) : ty;
        #pragma unroll
        for (int i = 0; i < 32; i += 8)
            O[(size_t)(c0 + i + hp) * C_ + fp] = round_tf32(tile[tx][ty + i]);
    }
}

// ---------------------------------------------------------------------------
// Launch
// ---------------------------------------------------------------------------
extern "C" void kernel_launch(void* const* d_in, const int* in_sizes, int n_in,
                              void* d_out, int out_size)
{
    const float* x  = (const float*)d_in[0];
    const float* Wq = (const float*)d_in[1];
    const float* Wk = (const float*)d_in[2];
    const float* Wv = (const float*)d_in[3];
    float* out = (float*)d_out;

    float* wtp;
    cudaGetSymbolAddress((void**)&wtp, g_WT);

    cudaFuncSetAttribute(proj_qk,  cudaFuncAttributeMaxDynamicSharedMemorySize, SMEM_TOTAL);
    cudaFuncSetAttribute(qk_projv, cudaFuncAttributeMaxDynamicSharedMemorySize, SMEM_TOTAL);
    cudaFuncSetAttribute(pv_mma,   cudaFuncAttributeMaxDynamicSharedMemorySize, SMEM_TOTAL);

    prep<<<16384 + 3072, 256>>>(x, Wq, Wk, Wv);

    dim3 gproj(H_ / BN, (B_ * T_) / BM, 2);
    proj_qk<<<gproj, NTHR, SMEM_TOTAL>>>(wtp, wtp + (size_t)H_ * C_);

    qk_projv<<<2112, NTHR, SMEM_TOTAL>>>(wtp + 2 * (size_t)H_ * C_);

    pv_mma<<<1024, NTHR, SMEM_TOTAL>>>(out);
}